// round 7
// baseline (speedup 1.0000x reference)
#include <cuda_runtime.h>
#include <cstdint>

#define N_Q 4096
#define NTHREADS 1024
#define CLUSTER 4
#define EVAL_PT_SCORE 0.05f
#define D2_THRESH 25.0f   // 5.0^2
#define NBR_CAP 6
#define OVF 255
#define HCAP 2560         // stripe+halo point capacity (expected ~1150)
#define WCAP 2048         // worklist capacity (expected ~460)
#define NBUCK 1024
#define NCELL 1152        // 18 rows * 64 cols
#define NCNT (NBUCK + NCELL)   // 2176 fused counters

// smem ~144.6 KB (see pointer carve-out below)
#define SMEM_BYTES 144644

__device__ __forceinline__ uint32_t smem_u32(const void* p) {
    uint32_t a;
    asm("{ .reg .u64 t; cvta.to.shared.u64 t, %1; cvt.u32.u64 %0, t; }"
        : "=r"(a) : "l"(p));
    return a;
}
__device__ __forceinline__ uint32_t mapa_rank(uint32_t addr, uint32_t r) {
    uint32_t o;
    asm("mapa.shared::cluster.u32 %0, %1, %2;" : "=r"(o) : "r"(addr), "r"(r));
    return o;
}
__device__ __forceinline__ void st_cl_u8(uint32_t addr, uint32_t v) {
    asm volatile("st.shared::cluster.u8 [%0], %1;" :: "r"(addr), "r"(v) : "memory");
}
__device__ __forceinline__ void st_cl_u32(uint32_t addr, uint32_t v) {
    asm volatile("st.shared::cluster.u32 [%0], %1;" :: "r"(addr), "r"(v) : "memory");
}
#define CLUSTER_SYNC() do { \
    asm volatile("barrier.cluster.arrive.aligned;" ::: "memory"); \
    asm volatile("barrier.cluster.wait.aligned;" ::: "memory"); } while (0)

__device__ __forceinline__ int warp_incl_scan(int v) {
    int lane = threadIdx.x & 31;
    #pragma unroll
    for (int o = 1; o < 32; o <<= 1) {
        int n = __shfl_up_sync(0xffffffffu, v, o);
        if (lane >= o) v += n;
    }
    return v;
}

__device__ __forceinline__ unsigned long long mk_key(float s, int i) {
    bool valid = (s >= EVAL_PT_SCORE);
    unsigned int fb = __float_as_uint(s);
    return valid
        ? ((((unsigned long long)fb) << 32) | (unsigned int)(N_Q - 1 - i))
        : (unsigned long long)(unsigned int)(N_Q - 1 - i);
}

__global__ void __launch_bounds__(NTHREADS, 1) __cluster_dims__(CLUSTER, 1, 1)
nms_kernel(const float* __restrict__ logits,
           const float* __restrict__ boxes,
           const float* __restrict__ ts,
           float* __restrict__ out) {
    const int cls = blockIdx.x / CLUSTER;     // 0 = end, 1 = junction
    const int rank = blockIdx.x & (CLUSTER - 1);
    const int tid = threadIdx.x;
    const int lane = tid & 31;
    const int wid = tid >> 5;
    const int rbase = 16 * rank - 1;          // stripe-local row 0 = cell row rbase

    extern __shared__ unsigned char sm[];
    uint4* hrec = (uint4*)sm;                                      // [HCAP]
    unsigned long long* skey = (unsigned long long*)(hrec + HCAP); // [N_Q]
    int* cs  = (int*)(skey + N_Q);                                 // [NCNT+1]
    int* ccu = cs + (NCNT + 1);                                    // [NCNT]
    int* warpsum = ccu + NCNT;                                     // [64]
    unsigned short* bpt   = (unsigned short*)(warpsum + 64);       // [N_Q]
    unsigned short* hidx  = bpt + N_Q;                             // [HCAP]
    unsigned short* hcell = hidx + HCAP;                           // [HCAP]
    unsigned short* wl    = hcell + HCAP;                          // [WCAP]
    unsigned short* nbr   = wl + WCAP;                             // [WCAP*NBR_CAP]
    unsigned char* stat   = (unsigned char*)(nbr + WCAP * NBR_CAP);// [N_Q]
    unsigned char* nbrcnt = stat + N_Q;                            // [WCAP]
    __shared__ int s_cnt[CLUSTER];
    __shared__ int s_wl, s_chg, s_pend;

    const float tw = ts[0], th = ts[1];

    // ---- zero fused counters ----
    for (int c = tid; c < NCNT + 1; c += NTHREADS) cs[c] = 0;
    if (tid == 0) s_wl = 0;
    __syncthreads();

    // ---- phase A: duplicated fast softmax over ALL 4096 (blocked, vector LDG) ----
    unsigned long long rkey[4];
    float rx[4], ry[4];
    int rb[4], rlc[4];
    {
        const float2* lg2 = (const float2*)(logits + 12 * tid);
        float2 L0 = lg2[0], L1 = lg2[1], L2 = lg2[2];
        float2 L3 = lg2[3], L4 = lg2[4], L5 = lg2[5];
        float lg[12] = {L0.x, L0.y, L1.x, L1.y, L2.x, L2.y,
                        L3.x, L3.y, L4.x, L4.y, L5.x, L5.y};
        const float4* bx4 = (const float4*)(boxes + 8 * tid);
        float4 B0 = bx4[0], B1 = bx4[1];
        float bx[8] = {B0.x, B0.y, B0.z, B0.w, B1.x, B1.y, B1.z, B1.w};
        bool own = ((tid >> 8) == rank);       // my 256-thread slab = my 1024 points
        #pragma unroll
        for (int k = 0; k < 4; k++) {
            int j = 4 * tid + k;
            float l0 = lg[3 * k], l1 = lg[3 * k + 1], l2 = lg[3 * k + 2];
            float m = fmaxf(l0, fmaxf(l1, l2));
            float e0 = __expf(l0 - m), e1 = __expf(l1 - m), e2 = __expf(l2 - m);
            float inv = __fdividef(1.0f, e0 + e1 + e2);
            float p0 = e0 * inv, p1 = e1 * inv, p2 = e2 * inv;
            float x = bx[2 * k] * tw;
            float y = bx[2 * k + 1] * th;
            float s = (cls == 0) ? p0 : p1;
            bool valid = (s >= EVAL_PT_SCORE);
            unsigned long long key = mk_key(s, j);
            rkey[k] = key; rx[k] = x; ry[k] = y;
            skey[j] = key;
            stat[j] = valid ? (unsigned char)0 : (unsigned char)2;
            rb[k] = min(NBUCK - 1, (int)(s * (float)NBUCK));
            if (valid) atomicAdd(&cs[rb[k]], 1);
            int cx = min(63, max(0, (int)(x * 0.125f)));
            int cy = min(63, max(0, (int)(y * 0.125f)));
            int lr = cy - rbase;
            rlc[k] = (lr >= 0 && lr < 18) ? (lr * 64 + cx) : -1;
            if (rlc[k] >= 0) atomicAdd(&cs[NBUCK + rlc[k]], 1);
            if (own) {
                if (cls == 0) {
                    out[5 * j + 0] = 1.0f - p2;
                    out[5 * j + 1] = x;
                    out[5 * j + 2] = y;
                    out[5 * j + 3] = 0.0f;
                } else {
                    out[5 * j + 4] = 0.0f;
                }
            }
        }
    }
    __syncthreads();

    // ---- single fused exclusive scan over 2176 counters (3/thread) ----
    {
        int i0 = 3 * tid, i1 = i0 + 1, i2 = i0 + 2;
        int v0 = (i0 < NCNT) ? cs[i0] : 0;
        int v1 = (i1 < NCNT) ? cs[i1] : 0;
        int v2 = (i2 < NCNT) ? cs[i2] : 0;
        int l = v0 + v1 + v2;
        int il = warp_incl_scan(l);
        if (lane == 31) warpsum[wid] = il;
        __syncthreads();
        if (wid == 0) warpsum[lane] = warp_incl_scan(warpsum[lane]);
        __syncthreads();
        int base = il - l + (wid ? warpsum[wid - 1] : 0);
        if (i0 < NCNT) { cs[i0] = base;            ccu[i0] = base; }
        if (i1 < NCNT) { cs[i1] = base + v0;       ccu[i1] = base + v0; }
        if (i2 < NCNT) { cs[i2] = base + v0 + v1;  ccu[i2] = base + v0 + v1; }
        if (tid == 0) cs[NCNT] = warpsum[31];
    }
    __syncthreads();
    const int nv = cs[NBUCK];            // total valid points
    const int htotal = cs[NCNT] - nv;    // stripe+halo points

    // ---- scatter: bucket list (valid) + stripe records ----
    #pragma unroll
    for (int k = 0; k < 4; k++) {
        int j = 4 * tid + k;
        if (rkey[k] >> 32) {
            int bp = atomicAdd(&ccu[rb[k]], 1);
            bpt[bp] = (unsigned short)j;
        }
        if (rlc[k] >= 0) {
            int pos = atomicAdd(&ccu[NBUCK + rlc[k]], 1) - nv;
            hrec[pos] = make_uint4((unsigned int)rkey[k],
                                   (unsigned int)(rkey[k] >> 32),
                                   __float_as_uint(rx[k]),
                                   __float_as_uint(ry[k]));
            hidx[pos] = (unsigned short)j;
            hcell[pos] = (unsigned short)rlc[k];
        }
    }
    __syncthreads();

    // ---- edge build for OWNED points (local rows 1..16) ----
    for (int p = tid; p < htotal; p += NTHREADS) {
        uint4 R = hrec[p];
        if (R.y == 0) continue;                   // invalid
        int lc = hcell[p];
        int lr = lc >> 6;
        if (lr < 1 || lr > 16) continue;          // halo-only
        unsigned long long kj = ((unsigned long long)R.y << 32) | R.x;
        float xj = __uint_as_float(R.z), yj = __uint_as_float(R.w);
        int cx = lc & 63;
        int x0 = max(cx - 1, 0), x1 = min(cx + 1, 63);
        unsigned short tmp[NBR_CAP];
        int cnt = 0;
        #pragma unroll
        for (int rr = lr - 1; rr <= lr + 1; rr++) {
            int qs = cs[NBUCK + rr * 64 + x0] - nv;
            int qe = cs[NBUCK + rr * 64 + x1 + 1] - nv;
            for (int q = qs; q < qe; q++) {
                uint4 C = hrec[q];
                unsigned long long ki = ((unsigned long long)C.y << 32) | C.x;
                if (ki <= kj) continue;           // lower rank / invalid / self
                float dx = __uint_as_float(C.z) - xj;
                float dy = __uint_as_float(C.w) - yj;
                if (dx * dx + dy * dy < D2_THRESH) {
                    if (cnt < NBR_CAP) tmp[cnt] = hidx[q];
                    cnt++;
                }
            }
        }
        int i = hidx[p];
        if (cnt == 0) {
            stat[i] = 1;
        } else {
            int w = atomicAdd(&s_wl, 1);
            wl[w] = (unsigned short)p;
            nbrcnt[w] = (cnt > NBR_CAP) ? (unsigned char)OVF : (unsigned char)cnt;
            #pragma unroll
            for (int k = 0; k < NBR_CAP; k++)
                if (k < cnt) nbr[w * NBR_CAP + k] = tmp[k];
        }
    }
    __syncthreads();
    const int nwl = s_wl;

    CLUSTER_SYNC();   // stat init complete cluster-wide before any remote store

    // boundary stat send: local row 1 (cy=16r) -> rank-1; row 16 -> rank+1
    #define SEND_BOUNDARY() do {                                              \
        if (rank > 0) {                                                       \
            int qs = cs[NBUCK + 64] - nv, qe = cs[NBUCK + 128] - nv;          \
            for (int p = qs + tid; p < qe; p += NTHREADS) {                   \
                int i = hidx[p];                                              \
                st_cl_u8(mapa_rank(smem_u32(&stat[i]), rank - 1), stat[i]);   \
            }                                                                 \
        }                                                                     \
        if (rank < CLUSTER - 1) {                                             \
            int qs = cs[NBUCK + 16 * 64] - nv, qe = cs[NBUCK + 17 * 64] - nv; \
            for (int p = qs + tid; p < qe; p += NTHREADS) {                   \
                int i = hidx[p];                                              \
                st_cl_u8(mapa_rank(smem_u32(&stat[i]), rank + 1), stat[i]);   \
            }                                                                 \
        }                                                                     \
    } while (0)

    // ---- outer rounds: local fixed point + boundary exchange ----
    while (true) {
        int pend;
        while (true) {
            if (tid == 0) { s_chg = 0; s_pend = 0; }
            __syncthreads();
            int lchg = 0, lpend = 0;
            for (int w = tid; w < nwl; w += NTHREADS) {
                int p = wl[w];
                int i = hidx[p];
                if (stat[i] != 0) continue;
                int c = nbrcnt[w];
                bool sup = false, pd = false;
                if (c != OVF) {
                    #pragma unroll 1
                    for (int k = 0; k < c; k++) {
                        unsigned char st = stat[nbr[w * NBR_CAP + k]];
                        if (st == 1) { sup = true; break; }
                        if (st == 0) pd = true;
                    }
                } else {
                    uint4 R = hrec[p];
                    unsigned long long kj = ((unsigned long long)R.y << 32) | R.x;
                    float xj = __uint_as_float(R.z), yj = __uint_as_float(R.w);
                    int lc = hcell[p];
                    int cx = lc & 63, lr = lc >> 6;
                    int x0 = max(cx - 1, 0), x1 = min(cx + 1, 63);
                    for (int rr = lr - 1; rr <= lr + 1 && !sup; rr++) {
                        int qs = cs[NBUCK + rr * 64 + x0] - nv;
                        int qe = cs[NBUCK + rr * 64 + x1 + 1] - nv;
                        for (int q = qs; q < qe; q++) {
                            uint4 C = hrec[q];
                            unsigned long long ki = ((unsigned long long)C.y << 32) | C.x;
                            if (ki <= kj) continue;
                            float dx = __uint_as_float(C.z) - xj;
                            float dy = __uint_as_float(C.w) - yj;
                            if (dx * dx + dy * dy < D2_THRESH) {
                                unsigned char st = stat[hidx[q]];
                                if (st == 1) { sup = true; break; }
                                if (st == 0) pd = true;
                            }
                        }
                    }
                }
                if (sup)      { stat[i] = 2; lchg++; }
                else if (!pd) { stat[i] = 1; lchg++; }
                else          lpend++;
            }
            if (lchg) atomicAdd(&s_chg, lchg);
            if (lpend) atomicAdd(&s_pend, lpend);
            __syncthreads();
            if (s_chg == 0) { pend = s_pend; break; }
        }
        SEND_BOUNDARY();
        if (tid == 0) {
            s_cnt[rank] = pend;
            uint32_t a = smem_u32(&s_cnt[rank]);
            #pragma unroll
            for (int r = 0; r < CLUSTER; r++)
                if (r != rank) st_cl_u32(mapa_rank(a, r), (unsigned int)pend);
        }
        CLUSTER_SYNC();
        if (s_cnt[0] + s_cnt[1] + s_cnt[2] + s_cnt[3] == 0) break;
    }

    // ---- owner writes outputs for owned retained points ----
    for (int p = tid; p < htotal; p += NTHREADS) {
        int lc = hcell[p];
        int lr = lc >> 6;
        if (lr < 1 || lr > 16) continue;          // not owned
        int i = hidx[p];
        if (stat[i] != 1) continue;
        uint4 R = hrec[p];
        unsigned long long kj = ((unsigned long long)R.y << 32) | R.x;
        float s = __uint_as_float(R.y);
        int b = min(NBUCK - 1, (int)(s * (float)NBUCK));
        int r = nv - cs[b + 1];
        int e = cs[b + 1];
        for (int q = cs[b]; q < e; q++) {
            if (skey[bpt[q]] > kj) r++;
        }
        out[5 * r + 3 + cls] = s;
    }
}

extern "C" void kernel_launch(void* const* d_in, const int* in_sizes, int n_in,
                              void* d_out, int out_size) {
    const float* logits = (const float*)d_in[0];   // [1,4096,3]
    const float* boxes  = (const float*)d_in[1];   // [1,4096,2]
    // d_in[2] = pred_gids (unused by reference)
    const float* ts     = (const float*)d_in[3];   // [1,2] = (w,h)
    float* out = (float*)d_out;                    // [1,4096,5]

    cudaFuncSetAttribute(nms_kernel,
                         cudaFuncAttributeMaxDynamicSharedMemorySize, SMEM_BYTES);
    nms_kernel<<<2 * CLUSTER, NTHREADS, SMEM_BYTES>>>(logits, boxes, ts, out);
}

// round 8
// speedup vs baseline: 1.0976x; 1.0976x over previous
#include <cuda_runtime.h>
#include <cstdint>

#define N_Q 4096
#define NTHREADS 1024
#define CLUSTER 4
#define EVAL_PT_SCORE 0.05f
#define D2_THRESH 25.0f   // 5.0^2
#define NBR_CAP 6
#define OVF 255
#define HCAP 2560         // stripe+halo point capacity (expected ~1150)
#define WCAP 2048         // worklist capacity (expected ~460)
#define NBUCK 1024
#define NCELL 1152        // 18 rows * 64 cols
#define NCNT (NBUCK + NCELL)   // 2176 fused counters

#define SMEM_BYTES 144644

__device__ __forceinline__ uint32_t smem_u32(const void* p) {
    uint32_t a;
    asm("{ .reg .u64 t; cvta.to.shared.u64 t, %1; cvt.u32.u64 %0, t; }"
        : "=r"(a) : "l"(p));
    return a;
}
__device__ __forceinline__ uint32_t mapa_rank(uint32_t addr, uint32_t r) {
    uint32_t o;
    asm("mapa.shared::cluster.u32 %0, %1, %2;" : "=r"(o) : "r"(addr), "r"(r));
    return o;
}
__device__ __forceinline__ void st_cl_u8(uint32_t addr, uint32_t v) {
    asm volatile("st.shared::cluster.u8 [%0], %1;" :: "r"(addr), "r"(v) : "memory");
}
#define CLUSTER_SYNC() do { \
    asm volatile("barrier.cluster.arrive.aligned;" ::: "memory"); \
    asm volatile("barrier.cluster.wait.aligned;" ::: "memory"); } while (0)

__device__ __forceinline__ int warp_incl_scan(int v) {
    int lane = threadIdx.x & 31;
    #pragma unroll
    for (int o = 1; o < 32; o <<= 1) {
        int n = __shfl_up_sync(0xffffffffu, v, o);
        if (lane >= o) v += n;
    }
    return v;
}

__device__ __forceinline__ unsigned long long mk_key(float s, int i) {
    bool valid = (s >= EVAL_PT_SCORE);
    unsigned int fb = __float_as_uint(s);
    return valid
        ? ((((unsigned long long)fb) << 32) | (unsigned int)(N_Q - 1 - i))
        : (unsigned long long)(unsigned int)(N_Q - 1 - i);
}

__global__ void __launch_bounds__(NTHREADS, 1) __cluster_dims__(CLUSTER, 1, 1)
nms_kernel(const float* __restrict__ logits,
           const float* __restrict__ boxes,
           const float* __restrict__ ts,
           float* __restrict__ out) {
    const int cls = blockIdx.x / CLUSTER;     // 0 = end, 1 = junction
    const int rank = blockIdx.x & (CLUSTER - 1);
    const int tid = threadIdx.x;
    const int lane = tid & 31;
    const int wid = tid >> 5;
    const int rbase = 16 * rank - 1;          // stripe-local row 0 = cell row rbase

    extern __shared__ unsigned char sm[];
    uint4* hrec = (uint4*)sm;                                      // [HCAP]
    unsigned long long* skey = (unsigned long long*)(hrec + HCAP); // [N_Q]
    int* cs  = (int*)(skey + N_Q);                                 // [NCNT+1]
    int* ccu = cs + (NCNT + 1);                                    // [NCNT]
    int* warpsum = ccu + NCNT;                                     // [64]
    unsigned short* bpt   = (unsigned short*)(warpsum + 64);       // [N_Q]
    unsigned short* hidx  = bpt + N_Q;                             // [HCAP]
    unsigned short* hcell = hidx + HCAP;                           // [HCAP]
    unsigned short* wl    = hcell + HCAP;                          // [WCAP]
    unsigned short* nbr   = wl + WCAP;                             // [WCAP*NBR_CAP]
    unsigned char* stat   = (unsigned char*)(nbr + WCAP * NBR_CAP);// [N_Q]
    unsigned char* nbrcnt = stat + N_Q;                            // [WCAP]
    volatile unsigned char* vstat = (volatile unsigned char*)stat;
    __shared__ int s_wl;

    const float tw = ts[0], th = ts[1];

    // ---- zero fused counters ----
    for (int c = tid; c < NCNT + 1; c += NTHREADS) cs[c] = 0;
    if (tid == 0) s_wl = 0;
    __syncthreads();

    // ---- phase A: duplicated fast softmax over ALL 4096 (blocked, vector LDG) ----
    unsigned long long rkey[4];
    float rx[4], ry[4];
    int rb[4], rlc[4];
    {
        const float2* lg2 = (const float2*)(logits + 12 * tid);
        float2 L0 = lg2[0], L1 = lg2[1], L2 = lg2[2];
        float2 L3 = lg2[3], L4 = lg2[4], L5 = lg2[5];
        float lg[12] = {L0.x, L0.y, L1.x, L1.y, L2.x, L2.y,
                        L3.x, L3.y, L4.x, L4.y, L5.x, L5.y};
        const float4* bx4 = (const float4*)(boxes + 8 * tid);
        float4 B0 = bx4[0], B1 = bx4[1];
        float bx[8] = {B0.x, B0.y, B0.z, B0.w, B1.x, B1.y, B1.z, B1.w};
        bool own = ((tid >> 8) == rank);       // my 256-thread slab = my 1024 points
        #pragma unroll
        for (int k = 0; k < 4; k++) {
            int j = 4 * tid + k;
            float l0 = lg[3 * k], l1 = lg[3 * k + 1], l2 = lg[3 * k + 2];
            float m = fmaxf(l0, fmaxf(l1, l2));
            float e0 = __expf(l0 - m), e1 = __expf(l1 - m), e2 = __expf(l2 - m);
            float inv = __fdividef(1.0f, e0 + e1 + e2);
            float p0 = e0 * inv, p1 = e1 * inv, p2 = e2 * inv;
            float x = bx[2 * k] * tw;
            float y = bx[2 * k + 1] * th;
            float s = (cls == 0) ? p0 : p1;
            bool valid = (s >= EVAL_PT_SCORE);
            unsigned long long key = mk_key(s, j);
            rkey[k] = key; rx[k] = x; ry[k] = y;
            skey[j] = key;
            stat[j] = valid ? (unsigned char)0 : (unsigned char)2;
            rb[k] = min(NBUCK - 1, (int)(s * (float)NBUCK));
            if (valid) atomicAdd(&cs[rb[k]], 1);
            int cx = min(63, max(0, (int)(x * 0.125f)));
            int cy = min(63, max(0, (int)(y * 0.125f)));
            int lr = cy - rbase;
            rlc[k] = (lr >= 0 && lr < 18) ? (lr * 64 + cx) : -1;
            if (rlc[k] >= 0) atomicAdd(&cs[NBUCK + rlc[k]], 1);
            if (own) {
                if (cls == 0) {
                    out[5 * j + 0] = 1.0f - p2;
                    out[5 * j + 1] = x;
                    out[5 * j + 2] = y;
                    out[5 * j + 3] = 0.0f;
                } else {
                    out[5 * j + 4] = 0.0f;
                }
            }
        }
    }
    __syncthreads();

    // ---- single fused exclusive scan over 2176 counters (3/thread) ----
    {
        int i0 = 3 * tid, i1 = i0 + 1, i2 = i0 + 2;
        int v0 = (i0 < NCNT) ? cs[i0] : 0;
        int v1 = (i1 < NCNT) ? cs[i1] : 0;
        int v2 = (i2 < NCNT) ? cs[i2] : 0;
        int l = v0 + v1 + v2;
        int il = warp_incl_scan(l);
        if (lane == 31) warpsum[wid] = il;
        __syncthreads();
        if (wid == 0) warpsum[lane] = warp_incl_scan(warpsum[lane]);
        __syncthreads();
        int base = il - l + (wid ? warpsum[wid - 1] : 0);
        if (i0 < NCNT) { cs[i0] = base;            ccu[i0] = base; }
        if (i1 < NCNT) { cs[i1] = base + v0;       ccu[i1] = base + v0; }
        if (i2 < NCNT) { cs[i2] = base + v0 + v1;  ccu[i2] = base + v0 + v1; }
        if (tid == 0) cs[NCNT] = warpsum[31];
    }
    __syncthreads();
    const int nv = cs[NBUCK];            // total valid points
    const int htotal = cs[NCNT] - nv;    // stripe+halo points

    // ---- scatter: bucket list (valid) + stripe records ----
    #pragma unroll
    for (int k = 0; k < 4; k++) {
        int j = 4 * tid + k;
        if (rkey[k] >> 32) {
            int bp = atomicAdd(&ccu[rb[k]], 1);
            bpt[bp] = (unsigned short)j;
        }
        if (rlc[k] >= 0) {
            int pos = atomicAdd(&ccu[NBUCK + rlc[k]], 1) - nv;
            hrec[pos] = make_uint4((unsigned int)rkey[k],
                                   (unsigned int)(rkey[k] >> 32),
                                   __float_as_uint(rx[k]),
                                   __float_as_uint(ry[k]));
            hidx[pos] = (unsigned short)j;
            hcell[pos] = (unsigned short)rlc[k];
        }
    }
    __syncthreads();

    // every CTA's stat[] fully initialized before any remote push lands
    CLUSTER_SYNC();

    // push resolved stat of a boundary-row point to the neighbor that sees it
    #define PUSH_STAT(i, lr, v) do {                                          \
        if ((lr) == 1 && rank > 0)                                            \
            st_cl_u8(mapa_rank(smem_u32(&stat[i]), rank - 1), (v));           \
        if ((lr) == 16 && rank < CLUSTER - 1)                                 \
            st_cl_u8(mapa_rank(smem_u32(&stat[i]), rank + 1), (v));           \
    } while (0)

    // ---- edge build for OWNED points (local rows 1..16), eager pushes ----
    for (int p = tid; p < htotal; p += NTHREADS) {
        uint4 R = hrec[p];
        if (R.y == 0) continue;                   // invalid
        int lc = hcell[p];
        int lr = lc >> 6;
        if (lr < 1 || lr > 16) continue;          // halo-only
        unsigned long long kj = ((unsigned long long)R.y << 32) | R.x;
        float xj = __uint_as_float(R.z), yj = __uint_as_float(R.w);
        int cx = lc & 63;
        int x0 = max(cx - 1, 0), x1 = min(cx + 1, 63);
        unsigned short tmp[NBR_CAP];
        int cnt = 0;
        #pragma unroll
        for (int rr = lr - 1; rr <= lr + 1; rr++) {
            int qs = cs[NBUCK + rr * 64 + x0] - nv;
            int qe = cs[NBUCK + rr * 64 + x1 + 1] - nv;
            for (int q = qs; q < qe; q++) {
                uint4 C = hrec[q];
                unsigned long long ki = ((unsigned long long)C.y << 32) | C.x;
                if (ki <= kj) continue;           // lower rank / invalid / self
                float dx = __uint_as_float(C.z) - xj;
                float dy = __uint_as_float(C.w) - yj;
                if (dx * dx + dy * dy < D2_THRESH) {
                    if (cnt < NBR_CAP) tmp[cnt] = hidx[q];
                    cnt++;
                }
            }
        }
        int i = hidx[p];
        if (cnt == 0) {
            stat[i] = 1;                          // top of its neighborhood
            PUSH_STAT(i, lr, 1u);
        } else {
            int w = atomicAdd(&s_wl, 1);
            wl[w] = (unsigned short)p;
            nbrcnt[w] = (cnt > NBR_CAP) ? (unsigned char)OVF : (unsigned char)cnt;
            #pragma unroll
            for (int k = 0; k < NBR_CAP; k++)
                if (k < cnt) nbr[w * NBR_CAP + k] = tmp[k];
        }
    }
    __syncthreads();
    const int nwl = s_wl;

    // ---- dataflow resolution: spin on volatile stats, no barriers ----
    for (int w = tid; w < nwl; w += NTHREADS) {
        int p = wl[w];
        int i = hidx[p];
        int lr = hcell[p] >> 6;
        int c = nbrcnt[w];
        unsigned int res = 0;
        if (c != OVF) {
            while (res == 0) {
                bool sup = false, pend = false;
                #pragma unroll 1
                for (int k = 0; k < c; k++) {
                    unsigned char st = vstat[nbr[w * NBR_CAP + k]];
                    if (st == 1) { sup = true; break; }
                    if (st == 0) pend = true;
                }
                if (sup) res = 2;
                else if (!pend) res = 1;
            }
        } else {
            uint4 R = hrec[p];
            unsigned long long kj = ((unsigned long long)R.y << 32) | R.x;
            float xj = __uint_as_float(R.z), yj = __uint_as_float(R.w);
            int lc = hcell[p];
            int cx = lc & 63;
            int x0 = max(cx - 1, 0), x1 = min(cx + 1, 63);
            while (res == 0) {
                bool sup = false, pend = false;
                for (int rr = lr - 1; rr <= lr + 1 && !sup; rr++) {
                    int qs = cs[NBUCK + rr * 64 + x0] - nv;
                    int qe = cs[NBUCK + rr * 64 + x1 + 1] - nv;
                    for (int q = qs; q < qe; q++) {
                        uint4 C = hrec[q];
                        unsigned long long ki = ((unsigned long long)C.y << 32) | C.x;
                        if (ki <= kj) continue;
                        float dx = __uint_as_float(C.z) - xj;
                        float dy = __uint_as_float(C.w) - yj;
                        if (dx * dx + dy * dy < D2_THRESH) {
                            unsigned char st = vstat[hidx[q]];
                            if (st == 1) { sup = true; break; }
                            if (st == 0) pend = true;
                        }
                    }
                }
                if (sup) res = 2;
                else if (!pend) res = 1;
            }
        }
        vstat[i] = (unsigned char)res;            // local visibility for spinners
        PUSH_STAT(i, lr, res);                    // remote visibility for neighbor
    }
    __syncthreads();

    // ---- owner writes outputs for owned retained points ----
    for (int p = tid; p < htotal; p += NTHREADS) {
        int lc = hcell[p];
        int lr = lc >> 6;
        if (lr < 1 || lr > 16) continue;          // not owned
        int i = hidx[p];
        if (stat[i] != 1) continue;
        uint4 R = hrec[p];
        unsigned long long kj = ((unsigned long long)R.y << 32) | R.x;
        float s = __uint_as_float(R.y);
        int b = min(NBUCK - 1, (int)(s * (float)NBUCK));
        int r = nv - cs[b + 1];
        int e = cs[b + 1];
        for (int q = cs[b]; q < e; q++) {
            if (skey[bpt[q]] > kj) r++;
        }
        out[5 * r + 3 + cls] = s;
    }

    // keep cluster smem alive until all peers' in-flight pushes land
    CLUSTER_SYNC();
}

extern "C" void kernel_launch(void* const* d_in, const int* in_sizes, int n_in,
                              void* d_out, int out_size) {
    const float* logits = (const float*)d_in[0];   // [1,4096,3]
    const float* boxes  = (const float*)d_in[1];   // [1,4096,2]
    // d_in[2] = pred_gids (unused by reference)
    const float* ts     = (const float*)d_in[3];   // [1,2] = (w,h)
    float* out = (float*)d_out;                    // [1,4096,5]

    cudaFuncSetAttribute(nms_kernel,
                         cudaFuncAttributeMaxDynamicSharedMemorySize, SMEM_BYTES);
    nms_kernel<<<2 * CLUSTER, NTHREADS, SMEM_BYTES>>>(logits, boxes, ts, out);
}